// round 11
// baseline (speedup 1.0000x reference)
#include <cuda_runtime.h>
#include <cuda_fp16.h>
#include <cstdint>

#define DI __device__ __forceinline__

constexpr int SEQ = 2048, HIDN = 1024, NHD = 16, ITR = 4096, HD = 256;

// ---------------- scratch (device globals; allocation-free) ----------------
__device__ __align__(16) __half g_xh [SEQ * HIDN];
__device__ __align__(16) __half g_wg [ITR * HIDN];
__device__ __align__(16) __half g_wu [ITR * HIDN];
__device__ __align__(16) __half g_wd [HIDN * ITR];
__device__ __align__(16) __half g_wq [NHD * HD * HD];
__device__ __align__(16) __half g_wk [NHD * HD * HD];
__device__ __align__(16) __half g_w1 [HD * 4 * HD];
__device__ __align__(16) __half g_w2 [HD * HD];
__device__ __align__(16) __half g_adjh[(size_t)NHD * SEQ * SEQ];
__device__ __align__(16) __half g_h  [SEQ * ITR];
__device__ __align__(16) __half g_hT [NHD * HD * SEQ];
__device__ __align__(16) __half g_q  [NHD * SEQ * HD];
__device__ __align__(16) __half g_k2 [NHD * SEQ * HD];
__device__ float                g_sc [(size_t)NHD * SEQ * SEQ];
__device__ __align__(16) __half g_ph [(size_t)NHD * SEQ * SEQ];
__device__ __align__(16) __half g_cb [(size_t)NHD * SEQ * 4 * HD];
__device__ __align__(16) __half g_t  [NHD * SEQ * HD];
__device__ __align__(16) __half g_gin[SEQ * ITR];

// ---------------- MUFU-free math ----------------
DI float exp_nm(float x){
  float t = fminf(fmaxf(x * 1.44269504f, -126.f), 126.f);
  float n = rintf(t);
  float y = (t - n) * 0.693147181f;
  float p = 1.f + y*(1.f + y*(0.5f + y*(0.166666667f + y*(0.0416666667f +
            y*(0.00833333333f + y*0.00138888889f)))));
  return p * __int_as_float(((int)n + 127) << 23);
}
DI float recip_nm(float d){
  float r = __int_as_float(0x7EF311C3u - __float_as_uint(d));
  r = r * (2.f - d*r); r = r * (2.f - d*r); r = r * (2.f - d*r);
  return r;
}
DI float log_nm(float x){ // x >= 1e-9
  int xi = __float_as_int(x);
  int e = ((xi >> 23) & 255) - 127;
  float m = __int_as_float((xi & 0x007FFFFF) | 0x3F800000);
  if (m > 1.33333334f){ m *= 0.5f; e += 1; }
  float u = m - 1.f;
  float p = u*(1.f + u*(-0.5f + u*(0.333333333f + u*(-0.25f + u*(0.2f +
            u*(-0.166666667f + u*(0.142857143f + u*(-0.125f +
            u*(0.111111111f - u*0.1f)))))))));
  return (float)e * 0.693147181f + p;
}
DI float silu_nm(float v){ return v * recip_nm(1.f + exp_nm(-v)); }

DI void mma16(float c[4], const uint32_t a[4], const uint32_t b[2]){
  asm volatile("mma.sync.aligned.m16n8k16.row.col.f32.f16.f16.f32 "
    "{%0,%1,%2,%3},{%4,%5,%6,%7},{%8,%9},{%0,%1,%2,%3};\n"
    : "+f"(c[0]),"+f"(c[1]),"+f"(c[2]),"+f"(c[3])
    : "r"(a[0]),"r"(a[1]),"r"(a[2]),"r"(a[3]),"r"(b[0]),"r"(b[1]));
}
DI void ldsm4(uint32_t d[4], uint32_t addr){
  asm volatile("ldmatrix.sync.aligned.m8n8.x4.shared.b16 {%0,%1,%2,%3}, [%4];"
    : "=r"(d[0]),"=r"(d[1]),"=r"(d[2]),"=r"(d[3]) : "r"(addr));
}
DI uint32_t cvta_s(const void* p){ return (uint32_t)__cvta_generic_to_shared(p); }
DI void cpa16(uint32_t dst, const void* src){
  asm volatile("cp.async.cg.shared.global [%0], [%1], 16;" :: "r"(dst), "l"(src));
}
DI void cpa_commit(){ asm volatile("cp.async.commit_group;" ::: "memory"); }
template<int N> DI void cpa_wait(){ asm volatile("cp.async.wait_group %0;" :: "n"(N) : "memory"); }

// ---------------- batched GEMM: C = A @ B^T, fp16 in gmem, cp.async 4-stage ----------------
// 128x128 CTA tile, 4 warps (2x2), 64x64 warp tile.
enum { E_RAW=0, E_SWIGLU=1, E_SCORES=2, E_SCALEH=3, E_SILU=4 };

struct GArg {
  const void* A; long long sA; int lda;   // half, element strides
  const void* B; long long sB; int ldb;   // half
  void*       C; long long sC; int ldc;   // CT
  const void* X; long long sX; int ldx;   // half
  const float* pvec;
  int K;
};

template<int EPI, typename CT>
DI void st2(const GArg& g, int b, long long rg, long long cg, float v0, float v1){
  float o0, o1;
  if (EPI == E_RAW){ o0 = v0; o1 = v1; }
  else if (EPI == E_SWIGLU){
    __half2 u = *(const __half2*)((const __half*)g.X + rg*(long long)g.ldx + cg);
    o0 = silu_nm(v0) * __half2float(u.x); o1 = silu_nm(v1) * __half2float(u.y);
  } else if (EPI == E_SCORES){
    __half2 a2 = *(const __half2*)((const __half*)g.X + (long long)b*g.sX + rg*(long long)g.ldx + cg);
    o0 = v0*0.0625f + log_nm(__half2float(a2.x) + 1e-9f);
    o1 = v1*0.0625f + log_nm(__half2float(a2.y) + 1e-9f);
  } else if (EPI == E_SCALEH){ float s = g.pvec[b]; o0 = v0*s; o1 = v1*s; }
  else { o0 = silu_nm(v0); o1 = silu_nm(v1); }
  CT* p = (CT*)g.C + (long long)b*g.sC + rg*(long long)g.ldc + cg;
  if constexpr (sizeof(CT) == 2) *(__half2*)p = __floats2half2_rn(o0, o1);
  else                           *(float2*)p  = make_float2(o0, o1);
}

constexpr int ROWH = 40;                       // halfs per smem row (80B)
constexpr int TILEH = 128 * ROWH;              // halfs per tile
constexpr int STAGEB = 2 * TILEH * 2;          // bytes per stage (A+B) = 20480
constexpr int NST = 4;
constexpr int GEMM_SMEM = NST * STAGEB;        // 81920

template<int EPI, typename CT>
__global__ void __launch_bounds__(128, 2) gemm_h(GArg g){
  extern __shared__ __half smh[];
  const int b = blockIdx.z;
  const __half* A = (const __half*)g.A + (long long)b*g.sA;
  const __half* B = (const __half*)g.B + (long long)b*g.sB;
  const int m0 = blockIdx.y * 128, n0 = blockIdx.x * 128;
  const int tid = threadIdx.x, lane = tid & 31, wid = tid >> 5;
  const int wm = wid & 1, wn = wid >> 1;       // 2x2 warps, 64x64 each
  const int ar = lane >> 2, ac = lane & 3;
  float acc[4][8][4] = {};

  const uint32_t smem0 = cvta_s(smh);
  // A ldsm4: d0=rows0-7/k0-7, d1=rows8-15/k0-7, d2=rows0-7/k8-15, d3=rows8-15/k8-15
  const uint32_t aBase = smem0 + (wm*64 + (lane & 7) + ((lane >> 3) & 1)*8)*(ROWH*2)
                       + ((lane >> 4) & 1)*16;
  // B ldsm4: d0=nt rows0-7/k0-7, d1=nt rows0-7/k8-15, d2=nt+1 rows/k0-7, d3=nt+1/k8-15
  const uint32_t bBase = smem0 + TILEH*2 + (wn*64 + (lane & 7) + ((lane >> 4) & 1)*8)*(ROWH*2)
                       + ((lane >> 3) & 1)*16;
  const int ktiles = g.K >> 5;

  auto issue = [&](int kt){
    if (kt < ktiles){
      int st = kt & (NST - 1);
      uint32_t da = smem0 + st*STAGEB + tid*(ROWH*2);
      uint32_t db = da + TILEH*2;
      const char* sa = (const char*)(A + (long long)(m0 + tid)*g.lda + kt*32);
      const char* sb = (const char*)(B + (long long)(n0 + tid)*g.ldb + kt*32);
      #pragma unroll
      for (int j = 0; j < 4; j++){
        cpa16(da + j*16, sa + j*16);
        cpa16(db + j*16, sb + j*16);
      }
    }
    cpa_commit();
  };

  issue(0); issue(1); issue(2);

  for (int kt = 0; kt < ktiles; kt++){
    cpa_wait<2>();
    __syncthreads();
    issue(kt + 3);   // fills stage (kt-1)&3 — all warps synced past reading it
    const uint32_t so = (uint32_t)(kt & (NST - 1)) * STAGEB;
    #pragma unroll
    for (int kk = 0; kk < 32; kk += 16){
      uint32_t af[4][4], bf[8][2];
      #pragma unroll
      for (int mt = 0; mt < 4; mt++)
        ldsm4(af[mt], aBase + so + mt*16*(ROWH*2) + kk*2);
      #pragma unroll
      for (int np = 0; np < 4; np++){
        uint32_t b4[4];
        ldsm4(b4, bBase + so + np*16*(ROWH*2) + kk*2);
        bf[np*2+0][0] = b4[0]; bf[np*2+0][1] = b4[1];
        bf[np*2+1][0] = b4[2]; bf[np*2+1][1] = b4[3];
      }
      #pragma unroll
      for (int mt = 0; mt < 4; mt++)
        #pragma unroll
        for (int nt = 0; nt < 8; nt++)
          mma16(acc[mt][nt], af[mt], bf[nt]);
    }
    __syncthreads();
  }

  #pragma unroll
  for (int mt = 0; mt < 4; mt++)
    #pragma unroll
    for (int nt = 0; nt < 8; nt++){
      long long rg = m0 + wm*64 + mt*16 + ar;
      long long cg = n0 + wn*64 + nt*8 + (ac << 1);
      st2<EPI, CT>(g, b, rg,   cg, acc[mt][nt][0], acc[mt][nt][1]);
      st2<EPI, CT>(g, b, rg+8, cg, acc[mt][nt][2], acc[mt][nt][3]);
    }
}

// ---------------- fp32 -> fp16 converter (n multiple of 8) ----------------
__global__ void kf2h(const float* __restrict__ in, __half* __restrict__ out, long long n8){
  long long i = (long long)blockIdx.x * 256 + threadIdx.x;
  if (i >= n8) return;
  float4 a = ((const float4*)in)[i*2], c = ((const float4*)in)[i*2+1];
  __half2 h0 = __floats2half2_rn(a.x,a.y), h1 = __floats2half2_rn(a.z,a.w);
  __half2 h2 = __floats2half2_rn(c.x,c.y), h3 = __floats2half2_rn(c.z,c.w);
  ((uint4*)out)[i] = make_uint4(*(uint32_t*)&h0, *(uint32_t*)&h1,
                                *(uint32_t*)&h2, *(uint32_t*)&h3);
}

// ---------------- per-head transpose: h (s, h*256+d) half -> hT (h, d, s) half ----------------
__global__ void ktrans(const __half* __restrict__ h, __half* __restrict__ hT){
  __shared__ __half t[32][34];
  int hd = blockIdx.z;
  int s0 = blockIdx.y * 32, d0 = blockIdx.x * 32;
  int tx = threadIdx.x, ty = threadIdx.y;
  #pragma unroll
  for (int i = 0; i < 32; i += 8)
    t[ty+i][tx] = h[(long long)(s0+ty+i)*4096 + hd*256 + d0 + tx];
  __syncthreads();
  #pragma unroll
  for (int i = 0; i < 32; i += 8)
    hT[(long long)hd*(256*2048) + (long long)(d0+ty+i)*2048 + s0 + tx] = t[tx][ty+i];
}

// ---------------- softmax: g_sc fp32 rows -> g_ph half ----------------
__global__ void ksoftmax(const float* __restrict__ sc, __half* __restrict__ ph){
  __shared__ float red[256];
  size_t row = blockIdx.x;
  const float* p = sc + row * 2048;
  __half* q = ph + row * 2048;
  int t = threadIdx.x;
  float x[8]; float mx = -1e30f;
  #pragma unroll
  for (int i = 0; i < 8; i++){ x[i] = p[t + (i << 8)]; mx = fmaxf(mx, x[i]); }
  red[t] = mx; __syncthreads();
  for (int s = 128; s > 0; s >>= 1){ if (t < s) red[t] = fmaxf(red[t], red[t+s]); __syncthreads(); }
  mx = red[0]; __syncthreads();
  float sum = 0.f;
  #pragma unroll
  for (int i = 0; i < 8; i++){ x[i] = exp_nm(x[i] - mx); sum += x[i]; }
  red[t] = sum; __syncthreads();
  for (int s = 128; s > 0; s >>= 1){ if (t < s) red[t] += red[t+s]; __syncthreads(); }
  float inv = recip_nm(red[0]);
  #pragma unroll
  for (int i = 0; i < 8; i++) q[t + (i << 8)] = __float2half_rn(x[i] * inv);
}

// ---------------- fill comb slices 0 (orig) and 2 (max), half ----------------
__global__ void kcomb(const __half* __restrict__ h, __half* __restrict__ comb,
                      const float* __restrict__ eps){
  long long i = (long long)blockIdx.x * 256 + threadIdx.x;
  int d = (int)(i & 255);
  long long sh = i >> 8;
  int s = (int)(sh & 2047);
  int hd = (int)(sh >> 11);
  float hv = __half2float(h[(long long)s * 4096 + hd * 256 + d]);
  long long base = (long long)hd * (2048 * 1024) + (long long)s * 1024 + d;
  comb[base]       = __float2half_rn((1.f + eps[hd]) * hv);
  comb[base + 512] = __float2half_rn(hv);
}

// ---------------- launch ----------------
extern "C" void kernel_launch(void* const* d_in, const int* in_sizes, int n_in,
                              void* d_out, int out_size){
  const float* x    = (const float*)d_in[0];
  const float* adj  = (const float*)d_in[1];
  const float* Wg   = (const float*)d_in[2];
  const float* Wu   = (const float*)d_in[3];
  const float* Wd   = (const float*)d_in[4];
  const float* eps  = (const float*)d_in[5];
  const float* alpha= (const float*)d_in[6];
  const float* Wq   = (const float*)d_in[7];
  const float* Wk   = (const float*)d_in[8];
  const float* W1   = (const float*)d_in[9];
  const float* W2   = (const float*)d_in[10];
  float* out = (float*)d_out;

  __half *pxh,*pwg,*pwu,*pwd,*pwq,*pwk,*pw1,*pw2,*padjh,*ph,*phT,*pq,*pk,*pph,*pcb,*pt,*pg;
  float *psc;
  cudaGetSymbolAddress((void**)&pxh,  g_xh);
  cudaGetSymbolAddress((void**)&pwg,  g_wg);
  cudaGetSymbolAddress((void**)&pwu,  g_wu);
  cudaGetSymbolAddress((void**)&pwd,  g_wd);
  cudaGetSymbolAddress((void**)&pwq,  g_wq);
  cudaGetSymbolAddress((void**)&pwk,  g_wk);
  cudaGetSymbolAddress((void**)&pw1,  g_w1);
  cudaGetSymbolAddress((void**)&pw2,  g_w2);
  cudaGetSymbolAddress((void**)&padjh,g_adjh);
  cudaGetSymbolAddress((void**)&ph,   g_h);
  cudaGetSymbolAddress((void**)&phT,  g_hT);
  cudaGetSymbolAddress((void**)&pq,   g_q);
  cudaGetSymbolAddress((void**)&pk,   g_k2);
  cudaGetSymbolAddress((void**)&psc,  g_sc);
  cudaGetSymbolAddress((void**)&pph,  g_ph);
  cudaGetSymbolAddress((void**)&pcb,  g_cb);
  cudaGetSymbolAddress((void**)&pt,   g_t);
  cudaGetSymbolAddress((void**)&pg,   g_gin);

  static cudaStream_t s1 = nullptr, s2 = nullptr;
  static cudaEvent_t ev0, evA, evT, ev4, ev8, evC, evH;
  static bool init_done = false;
  if (!init_done){
    cudaFuncSetAttribute(gemm_h<E_RAW,__half>,    cudaFuncAttributeMaxDynamicSharedMemorySize, GEMM_SMEM);
    cudaFuncSetAttribute(gemm_h<E_RAW,float>,     cudaFuncAttributeMaxDynamicSharedMemorySize, GEMM_SMEM);
    cudaFuncSetAttribute(gemm_h<E_SWIGLU,__half>, cudaFuncAttributeMaxDynamicSharedMemorySize, GEMM_SMEM);
    cudaFuncSetAttribute(gemm_h<E_SCORES,float>,  cudaFuncAttributeMaxDynamicSharedMemorySize, GEMM_SMEM);
    cudaFuncSetAttribute(gemm_h<E_SCALEH,__half>, cudaFuncAttributeMaxDynamicSharedMemorySize, GEMM_SMEM);
    cudaFuncSetAttribute(gemm_h<E_SILU,__half>,   cudaFuncAttributeMaxDynamicSharedMemorySize, GEMM_SMEM);
    cudaStreamCreateWithFlags(&s1, cudaStreamNonBlocking);
    cudaStreamCreateWithFlags(&s2, cudaStreamNonBlocking);
    cudaEventCreateWithFlags(&ev0, cudaEventDisableTiming);
    cudaEventCreateWithFlags(&evA, cudaEventDisableTiming);
    cudaEventCreateWithFlags(&evT, cudaEventDisableTiming);
    cudaEventCreateWithFlags(&ev4, cudaEventDisableTiming);
    cudaEventCreateWithFlags(&ev8, cudaEventDisableTiming);
    cudaEventCreateWithFlags(&evC, cudaEventDisableTiming);
    cudaEventCreateWithFlags(&evH, cudaEventDisableTiming);
    init_done = true;
  }
  cudaStream_t s0 = 0;
  auto cvt = [](cudaStream_t s, const float* src, __half* dst, long long n){
    long long n8 = n >> 3;
    kf2h<<<(unsigned)((n8 + 255)/256), 256, 0, s>>>(src, dst, n8);
  };

  // root the fork in the captured stream
  cudaEventRecord(ev0, s0);

  // s1: adjacency -> half (biggest prepass)
  cudaStreamWaitEvent(s1, ev0, 0);
  cvt(s1, adj, padjh, (long long)NHD*SEQ*SEQ);
  cudaEventRecord(evH, s1);

  // s2: Wk -> half
  cudaStreamWaitEvent(s2, ev0, 0);
  cvt(s2, Wk, pwk, (long long)NHD*HD*HD);

  // s0: input + weight conversions
  cvt(s0, x,  pxh, (long long)SEQ*HIDN);
  cvt(s0, Wu, pwu, (long long)ITR*HIDN);
  cvt(s0, Wg, pwg, (long long)ITR*HIDN);
  cvt(s0, Wq, pwq, (long long)NHD*HD*HD);
  cvt(s0, W1, pw1, (long long)HD*4*HD);
  cvt(s0, W2, pw2, (long long)HD*HD);
  cvt(s0, Wd, pwd, (long long)HIDN*ITR);

  GArg a; a.pvec = nullptr; a.X = nullptr; a.sX = 0; a.ldx = 0;

  // s0: 1) U = xh @ Wu^T -> g_gin(half) ; 2) h = silu(xh@Wg^T)*U -> g_h(half)
  a.A=pxh; a.sA=0; a.lda=1024; a.B=pwu; a.sB=0; a.ldb=1024;
  a.C=pg;  a.sC=0; a.ldc=4096; a.K=1024;
  gemm_h<E_RAW,__half><<<dim3(32,16,1), 128, GEMM_SMEM, s0>>>(a);
  a.B=pwg; a.C=ph; a.X=pg; a.sX=0; a.ldx=4096;
  gemm_h<E_SWIGLU,__half><<<dim3(32,16,1), 128, GEMM_SMEM, s0>>>(a);
  cudaEventRecord(evA, s0);

  // s1: ktrans -> stage 8 (adjh @ hT)
  cudaStreamWaitEvent(s1, evA, 0);
  ktrans<<<dim3(8,64,16), dim3(32,8), 0, s1>>>(ph, phT);
  cudaEventRecord(evT, s1);
  {
    GArg a8; a8.pvec = alpha; a8.X = nullptr; a8.sX = 0; a8.ldx = 0;
    a8.A=padjh; a8.sA=(long long)2048*2048; a8.lda=2048;
    a8.B=phT;   a8.sB=(long long)256*2048;  a8.ldb=2048;
    a8.C=pcb+256; a8.sC=(long long)2048*1024; a8.ldc=1024; a8.K=2048;
    gemm_h<E_SCALEH,__half><<<dim3(2,16,16), 128, GEMM_SMEM, s1>>>(a8);
  }
  cudaEventRecord(ev8, s1);

  // s2: stage 4 (K proj) -> kcomb
  cudaStreamWaitEvent(s2, evA, 0);
  {
    GArg a4; a4.pvec = nullptr; a4.X = nullptr; a4.sX = 0; a4.ldx = 0;
    a4.A=ph; a4.sA=256; a4.lda=4096; a4.B=pwk; a4.sB=65536; a4.ldb=256;
    a4.C=pk; a4.sC=(long long)2048*256; a4.ldc=256; a4.K=256;
    gemm_h<E_RAW,__half><<<dim3(2,16,16), 128, GEMM_SMEM, s2>>>(a4);
  }
  cudaEventRecord(ev4, s2);
  kcomb<<<32768, 256, 0, s2>>>(ph, pcb, eps);
  cudaEventRecord(evC, s2);

  // s0: 3) Q proj
  a.A=ph; a.sA=256; a.lda=4096; a.B=pwq; a.sB=65536; a.ldb=256;
  a.C=pq; a.sC=(long long)2048*256; a.ldc=256; a.K=256; a.X=nullptr;
  gemm_h<E_RAW,__half><<<dim3(2,16,16), 128, GEMM_SMEM, s0>>>(a);

  // s0: 5) scores = Q @ K^T / 16 + log(adjh + 1e-9) -> g_sc (fp32)
  cudaStreamWaitEvent(s0, ev4, 0);
  cudaStreamWaitEvent(s0, evH, 0);
  a.A=pq; a.sA=(long long)2048*256; a.lda=256;
  a.B=pk; a.sB=(long long)2048*256; a.ldb=256;
  a.C=psc; a.sC=(long long)2048*2048; a.ldc=2048; a.K=256;
  a.X=padjh; a.sX=(long long)2048*2048; a.ldx=2048;
  gemm_h<E_SCORES,float><<<dim3(16,16,16), 128, GEMM_SMEM, s0>>>(a);

  // s0: 6) softmax -> g_ph (half)
  ksoftmax<<<NHD*SEQ, 256, 0, s0>>>(psc, pph);

  // s0: 9) attn_agg = P @ hT^T  (needs hT from s1)
  cudaStreamWaitEvent(s0, evT, 0);
  a.A=pph; a.sA=(long long)2048*2048; a.lda=2048;
  a.B=phT; a.sB=(long long)256*2048;  a.ldb=2048;
  a.C=pcb+768; a.sC=(long long)2048*1024; a.ldc=1024; a.K=2048;
  a.X=nullptr;
  gemm_h<E_RAW,__half><<<dim3(2,16,16), 128, GEMM_SMEM, s0>>>(a);

  // join
  cudaStreamWaitEvent(s0, ev8, 0);
  cudaStreamWaitEvent(s0, evC, 0);

  // s0: 10) t = silu(comb @ W1^T)
  a.A=pcb; a.sA=(long long)2048*1024; a.lda=1024;
  a.B=pw1; a.sB=0; a.ldb=1024;
  a.C=pt;  a.sC=(long long)2048*256; a.ldc=256; a.K=1024;
  gemm_h<E_SILU,__half><<<dim3(2,16,16), 128, GEMM_SMEM, s0>>>(a);

  // s0: 11) gin = t @ W2^T (head-interleaved)
  a.A=pt; a.sA=(long long)2048*256; a.lda=256;
  a.B=pw2; a.sB=0; a.ldb=256;
  a.C=pg; a.sC=256; a.ldc=4096; a.K=256;
  gemm_h<E_RAW,__half><<<dim3(2,16,16), 128, GEMM_SMEM, s0>>>(a);

  // s0: 12) out = gin @ Wd^T (fp32 out)
  a.A=pg;  a.sA=0; a.lda=4096;
  a.B=pwd; a.sB=0; a.ldb=4096;
  a.C=out; a.sC=0; a.ldc=1024; a.K=4096;
  gemm_h<E_RAW,float><<<dim3(8,16,1), 128, GEMM_SMEM, s0>>>(a);
}

// round 12
// speedup vs baseline: 1.3194x; 1.3194x over previous
#include <cuda_runtime.h>
#include <cuda_fp16.h>
#include <cstdint>

#define DI __device__ __forceinline__

constexpr int SEQ = 2048, HIDN = 1024, NHD = 16, ITR = 4096, HD = 256;

// ---------------- scratch (device globals; allocation-free) ----------------
__device__ __align__(16) __half g_xh [SEQ * HIDN];
__device__ __align__(16) __half g_wg [ITR * HIDN];
__device__ __align__(16) __half g_wu [ITR * HIDN];
__device__ __align__(16) __half g_wd [HIDN * ITR];
__device__ __align__(16) __half g_wq [NHD * HD * HD];
__device__ __align__(16) __half g_wk [NHD * HD * HD];
__device__ __align__(16) __half g_w1 [HD * 4 * HD];
__device__ __align__(16) __half g_w2 [HD * HD];
__device__ __align__(16) __half g_adjh[(size_t)NHD * SEQ * SEQ];
__device__ __align__(16) __half g_h  [SEQ * ITR];
__device__ __align__(16) __half g_hT [NHD * HD * SEQ];
__device__ __align__(16) __half g_q  [NHD * SEQ * HD];
__device__ __align__(16) __half g_k2 [NHD * SEQ * HD];
__device__ __align__(16) __half g_ph [(size_t)NHD * SEQ * SEQ];   // unnormalized P (half)
__device__ float                g_rs [NHD * SEQ];                  // reciprocal row sums
__device__ __align__(16) __half g_cb [(size_t)NHD * SEQ * 4 * HD];
__device__ __align__(16) __half g_t  [NHD * SEQ * HD];
__device__ __align__(16) __half g_gin[SEQ * ITR];

// ---------------- MUFU-free math ----------------
DI float exp_nm(float x){
  float t = fminf(fmaxf(x * 1.44269504f, -126.f), 126.f);
  float n = rintf(t);
  float y = (t - n) * 0.693147181f;
  float p = 1.f + y*(1.f + y*(0.5f + y*(0.166666667f + y*(0.0416666667f +
            y*(0.00833333333f + y*0.00138888889f)))));
  return p * __int_as_float(((int)n + 127) << 23);
}
DI float recip_nm(float d){
  float r = __int_as_float(0x7EF311C3u - __float_as_uint(d));
  r = r * (2.f - d*r); r = r * (2.f - d*r); r = r * (2.f - d*r);
  return r;
}
DI float silu_nm(float v){ return v * recip_nm(1.f + exp_nm(-v)); }

DI void mma16(float c[4], const uint32_t a[4], const uint32_t b[2]){
  asm volatile("mma.sync.aligned.m16n8k16.row.col.f32.f16.f16.f32 "
    "{%0,%1,%2,%3},{%4,%5,%6,%7},{%8,%9},{%0,%1,%2,%3};\n"
    : "+f"(c[0]),"+f"(c[1]),"+f"(c[2]),"+f"(c[3])
    : "r"(a[0]),"r"(a[1]),"r"(a[2]),"r"(a[3]),"r"(b[0]),"r"(b[1]));
}
DI void ldsm4(uint32_t d[4], uint32_t addr){
  asm volatile("ldmatrix.sync.aligned.m8n8.x4.shared.b16 {%0,%1,%2,%3}, [%4];"
    : "=r"(d[0]),"=r"(d[1]),"=r"(d[2]),"=r"(d[3]) : "r"(addr));
}
DI void ldsm2(uint32_t d[2], uint32_t addr){
  asm volatile("ldmatrix.sync.aligned.m8n8.x2.shared.b16 {%0,%1}, [%2];"
    : "=r"(d[0]),"=r"(d[1]) : "r"(addr));
}
DI uint32_t cvta_s(const void* p){ return (uint32_t)__cvta_generic_to_shared(p); }
DI void cpa16(uint32_t dst, const void* src){
  asm volatile("cp.async.cg.shared.global [%0], [%1], 16;" :: "r"(dst), "l"(src));
}
DI void cpa_commit(){ asm volatile("cp.async.commit_group;" ::: "memory"); }
template<int N> DI void cpa_wait(){ asm volatile("cp.async.wait_group %0;" :: "n"(N) : "memory"); }

// ---------------- batched GEMM: C = A @ B^T, fp16 in gmem, cp.async 4-stage ----------------
// 128x128 CTA tile, 8 warps (2x4), 64x32 warp tile.  (R10 champion config)
enum { E_RAW=0, E_SWIGLU=1, E_PEXP=2, E_SCALEH=3, E_SILU=4, E_RSCALE=5 };

struct GArg {
  const void* A; long long sA; int lda;   // half, element strides
  const void* B; long long sB; int ldb;   // half
  void*       C; long long sC; int ldc;   // CT
  const void* X; long long sX; int ldx;   // half
  const float* pvec;                      // per-batch scale
  const float* rvec;                      // per-row scale (b*SEQ + row)
  int K;
};

template<int EPI, typename CT>
DI void st2(const GArg& g, int b, long long rg, long long cg, float v0, float v1){
  float o0, o1;
  if (EPI == E_RAW){ o0 = v0; o1 = v1; }
  else if (EPI == E_SWIGLU){
    __half2 u = *(const __half2*)((const __half*)g.X + rg*(long long)g.ldx + cg);
    o0 = silu_nm(v0) * __half2float(u.x); o1 = silu_nm(v1) * __half2float(u.y);
  } else if (EPI == E_PEXP){
    __half2 a2 = *(const __half2*)((const __half*)g.X + (long long)b*g.sX + rg*(long long)g.ldx + cg);
    o0 = exp_nm(v0*0.0625f) * (__half2float(a2.x) + 1e-9f);
    o1 = exp_nm(v1*0.0625f) * (__half2float(a2.y) + 1e-9f);
  } else if (EPI == E_SCALEH){ float s = g.pvec[b]; o0 = v0*s; o1 = v1*s; }
  else if (EPI == E_RSCALE){ float s = g.rvec[(long long)b*SEQ + rg]; o0 = v0*s; o1 = v1*s; }
  else { o0 = silu_nm(v0); o1 = silu_nm(v1); }
  CT* p = (CT*)g.C + (long long)b*g.sC + rg*(long long)g.ldc + cg;
  if constexpr (sizeof(CT) == 2) *(__half2*)p = __floats2half2_rn(o0, o1);
  else                           *(float2*)p  = make_float2(o0, o1);
}

constexpr int ROWH = 40;                       // halfs per smem row (80B)
constexpr int TILEH = 128 * ROWH;              // halfs per tile
constexpr int STAGEB = 2 * TILEH * 2;          // bytes per stage (A+B) = 20480
constexpr int NST = 4;
constexpr int GEMM_SMEM = NST * STAGEB;        // 81920

template<int EPI, typename CT>
__global__ void __launch_bounds__(256, 2) gemm_h(GArg g){
  extern __shared__ __half smh[];
  const int b = blockIdx.z;
  const __half* A = (const __half*)g.A + (long long)b*g.sA;
  const __half* B = (const __half*)g.B + (long long)b*g.sB;
  const int m0 = blockIdx.y * 128, n0 = blockIdx.x * 128;
  const int tid = threadIdx.x, lane = tid & 31, wid = tid >> 5;
  const int wm = wid & 1, wn = wid >> 1;
  const int ar = lane >> 2, ac = lane & 3;
  float acc[4][4][4] = {};

  const int rF = tid >> 1;              // 0..127
  const int cB = (tid & 1) * 32;        // byte col base {0,32}

  const uint32_t smem0 = cvta_s(smh);
  const uint32_t aBase = smem0 + (wm*64 + (lane & 7) + ((lane >> 3) & 1)*8)*(ROWH*2)
                       + ((lane >> 4) & 1)*16;
  const uint32_t bBase = smem0 + TILEH*2 + (wn*32 + (lane & 7))*(ROWH*2)
                       + ((lane >> 3) & 1)*16;
  const int ktiles = g.K >> 5;

  auto issue = [&](int kt){
    if (kt < ktiles){
      int st = kt & (NST - 1);
      uint32_t ds = smem0 + st*STAGEB + rF*(ROWH*2) + cB;
      const char* sa = (const char*)(A + (long long)(m0 + rF)*g.lda + kt*32) + cB;
      const char* sb = (const char*)(B + (long long)(n0 + rF)*g.ldb + kt*32) + cB;
      cpa16(ds,             sa);
      cpa16(ds + 16,        sa + 16);
      cpa16(ds + TILEH*2,      sb);
      cpa16(ds + TILEH*2 + 16, sb + 16);
    }
    cpa_commit();
  };

  issue(0); issue(1); issue(2);

  for (int kt = 0; kt < ktiles; kt++){
    cpa_wait<2>();
    __syncthreads();
    issue(kt + 3);
    const uint32_t so = (uint32_t)(kt & (NST - 1)) * STAGEB;
    #pragma unroll
    for (int kk = 0; kk < 32; kk += 16){
      uint32_t af[4][4], bf[4][2];
      #pragma unroll
      for (int mt = 0; mt < 4; mt++)
        ldsm4(af[mt], aBase + so + mt*16*(ROWH*2) + kk*2);
      #pragma unroll
      for (int nt = 0; nt < 4; nt++)
        ldsm2(bf[nt], bBase + so + nt*8*(ROWH*2) + kk*2);
      #pragma unroll
      for (int mt = 0; mt < 4; mt++)
        #pragma unroll
        for (int nt = 0; nt < 4; nt++)
          mma16(acc[mt][nt], af[mt], bf[nt]);
    }
    __syncthreads();
  }

  #pragma unroll
  for (int mt = 0; mt < 4; mt++)
    #pragma unroll
    for (int nt = 0; nt < 4; nt++){
      long long rg = m0 + wm*64 + mt*16 + ar;
      long long cg = n0 + wn*32 + nt*8 + (ac << 1);
      st2<EPI, CT>(g, b, rg,   cg, acc[mt][nt][0], acc[mt][nt][1]);
      st2<EPI, CT>(g, b, rg+8, cg, acc[mt][nt][2], acc[mt][nt][3]);
    }
}

// ---------------- fp32 -> fp16 converter (n multiple of 8) ----------------
__global__ void kf2h(const float* __restrict__ in, __half* __restrict__ out, long long n8){
  long long i = (long long)blockIdx.x * 256 + threadIdx.x;
  if (i >= n8) return;
  float4 a = ((const float4*)in)[i*2], c = ((const float4*)in)[i*2+1];
  __half2 h0 = __floats2half2_rn(a.x,a.y), h1 = __floats2half2_rn(a.z,a.w);
  __half2 h2 = __floats2half2_rn(c.x,c.y), h3 = __floats2half2_rn(c.z,c.w);
  ((uint4*)out)[i] = make_uint4(*(uint32_t*)&h0, *(uint32_t*)&h1,
                                *(uint32_t*)&h2, *(uint32_t*)&h3);
}

// ---------------- per-head transpose: h (s, h*256+d) half -> hT (h, d, s) half ----------------
__global__ void ktrans(const __half* __restrict__ h, __half* __restrict__ hT){
  __shared__ __half t[32][34];
  int hd = blockIdx.z;
  int s0 = blockIdx.y * 32, d0 = blockIdx.x * 32;
  int tx = threadIdx.x, ty = threadIdx.y;
  #pragma unroll
  for (int i = 0; i < 32; i += 8)
    t[ty+i][tx] = h[(long long)(s0+ty+i)*4096 + hd*256 + d0 + tx];
  __syncthreads();
  #pragma unroll
  for (int i = 0; i < 32; i += 8)
    hT[(long long)hd*(256*2048) + (long long)(d0+ty+i)*2048 + s0 + tx] = t[tx][ty+i];
}

// ---------------- row sums of unnormalized P -> reciprocal ----------------
__global__ void ksum(const __half* __restrict__ ph, float* __restrict__ rs){
  __shared__ float red[256];
  size_t row = blockIdx.x;
  const __half2* p = (const __half2*)(ph + row * 2048);
  int t = threadIdx.x;
  float s = 0.f;
  #pragma unroll
  for (int i = 0; i < 4; i++){
    __half2 v = p[t + (i << 8)];
    s += __half2float(v.x) + __half2float(v.y);
  }
  red[t] = s; __syncthreads();
  for (int k = 128; k > 0; k >>= 1){ if (t < k) red[t] += red[t+k]; __syncthreads(); }
  if (t == 0) rs[row] = recip_nm(red[0]);
}

// ---------------- fill comb slices 0 (orig) and 2 (max), half ----------------
__global__ void kcomb(const __half* __restrict__ h, __half* __restrict__ comb,
                      const float* __restrict__ eps){
  long long i = (long long)blockIdx.x * 256 + threadIdx.x;
  int d = (int)(i & 255);
  long long sh = i >> 8;
  int s = (int)(sh & 2047);
  int hd = (int)(sh >> 11);
  float hv = __half2float(h[(long long)s * 4096 + hd * 256 + d]);
  long long base = (long long)hd * (2048 * 1024) + (long long)s * 1024 + d;
  comb[base]       = __float2half_rn((1.f + eps[hd]) * hv);
  comb[base + 512] = __float2half_rn(hv);
}

// ---------------- launch ----------------
extern "C" void kernel_launch(void* const* d_in, const int* in_sizes, int n_in,
                              void* d_out, int out_size){
  const float* x    = (const float*)d_in[0];
  const float* adj  = (const float*)d_in[1];
  const float* Wg   = (const float*)d_in[2];
  const float* Wu   = (const float*)d_in[3];
  const float* Wd   = (const float*)d_in[4];
  const float* eps  = (const float*)d_in[5];
  const float* alpha= (const float*)d_in[6];
  const float* Wq   = (const float*)d_in[7];
  const float* Wk   = (const float*)d_in[8];
  const float* W1   = (const float*)d_in[9];
  const float* W2   = (const float*)d_in[10];
  float* out = (float*)d_out;

  __half *pxh,*pwg,*pwu,*pwd,*pwq,*pwk,*pw1,*pw2,*padjh,*ph,*phT,*pq,*pk,*pph,*pcb,*pt,*pg;
  float *prs;
  cudaGetSymbolAddress((void**)&pxh,  g_xh);
  cudaGetSymbolAddress((void**)&pwg,  g_wg);
  cudaGetSymbolAddress((void**)&pwu,  g_wu);
  cudaGetSymbolAddress((void**)&pwd,  g_wd);
  cudaGetSymbolAddress((void**)&pwq,  g_wq);
  cudaGetSymbolAddress((void**)&pwk,  g_wk);
  cudaGetSymbolAddress((void**)&pw1,  g_w1);
  cudaGetSymbolAddress((void**)&pw2,  g_w2);
  cudaGetSymbolAddress((void**)&padjh,g_adjh);
  cudaGetSymbolAddress((void**)&ph,   g_h);
  cudaGetSymbolAddress((void**)&phT,  g_hT);
  cudaGetSymbolAddress((void**)&pq,   g_q);
  cudaGetSymbolAddress((void**)&pk,   g_k2);
  cudaGetSymbolAddress((void**)&pph,  g_ph);
  cudaGetSymbolAddress((void**)&prs,  g_rs);
  cudaGetSymbolAddress((void**)&pcb,  g_cb);
  cudaGetSymbolAddress((void**)&pt,   g_t);
  cudaGetSymbolAddress((void**)&pg,   g_gin);

  static cudaStream_t s1 = nullptr, s2 = nullptr;
  static cudaEvent_t ev0, evA, evT, ev4, ev8, evC, evH;
  static bool init_done = false;
  if (!init_done){
    cudaFuncSetAttribute(gemm_h<E_RAW,__half>,    cudaFuncAttributeMaxDynamicSharedMemorySize, GEMM_SMEM);
    cudaFuncSetAttribute(gemm_h<E_RAW,float>,     cudaFuncAttributeMaxDynamicSharedMemorySize, GEMM_SMEM);
    cudaFuncSetAttribute(gemm_h<E_SWIGLU,__half>, cudaFuncAttributeMaxDynamicSharedMemorySize, GEMM_SMEM);
    cudaFuncSetAttribute(gemm_h<E_PEXP,__half>,   cudaFuncAttributeMaxDynamicSharedMemorySize, GEMM_SMEM);
    cudaFuncSetAttribute(gemm_h<E_SCALEH,__half>, cudaFuncAttributeMaxDynamicSharedMemorySize, GEMM_SMEM);
    cudaFuncSetAttribute(gemm_h<E_RSCALE,__half>, cudaFuncAttributeMaxDynamicSharedMemorySize, GEMM_SMEM);
    cudaFuncSetAttribute(gemm_h<E_SILU,__half>,   cudaFuncAttributeMaxDynamicSharedMemorySize, GEMM_SMEM);
    cudaStreamCreateWithFlags(&s1, cudaStreamNonBlocking);
    cudaStreamCreateWithFlags(&s2, cudaStreamNonBlocking);
    cudaEventCreateWithFlags(&ev0, cudaEventDisableTiming);
    cudaEventCreateWithFlags(&evA, cudaEventDisableTiming);
    cudaEventCreateWithFlags(&evT, cudaEventDisableTiming);
    cudaEventCreateWithFlags(&ev4, cudaEventDisableTiming);
    cudaEventCreateWithFlags(&ev8, cudaEventDisableTiming);
    cudaEventCreateWithFlags(&evC, cudaEventDisableTiming);
    cudaEventCreateWithFlags(&evH, cudaEventDisableTiming);
    init_done = true;
  }
  cudaStream_t s0 = 0;
  auto cvt = [](cudaStream_t s, const float* src, __half* dst, long long n){
    long long n8 = n >> 3;
    kf2h<<<(unsigned)((n8 + 255)/256), 256, 0, s>>>(src, dst, n8);
  };

  // root the fork in the captured stream
  cudaEventRecord(ev0, s0);

  // s1: adjacency -> half (biggest prepass)
  cudaStreamWaitEvent(s1, ev0, 0);
  cvt(s1, adj, padjh, (long long)NHD*SEQ*SEQ);
  cudaEventRecord(evH, s1);

  // s2: Wk -> half
  cudaStreamWaitEvent(s2, ev0, 0);
  cvt(s2, Wk, pwk, (long long)NHD*HD*HD);

  // s0: input + weight conversions
  cvt(s0, x,  pxh, (long long)SEQ*HIDN);
  cvt(s0, Wu, pwu, (long long)ITR*HIDN);
  cvt(s0, Wg, pwg, (long long)ITR*HIDN);
  cvt(s0, Wq, pwq, (long long)NHD*HD*HD);
  cvt(s0, W1, pw1, (long long)HD*4*HD);
  cvt(s0, W2, pw2, (long long)HD*HD);
  cvt(s0, Wd, pwd, (long long)HIDN*ITR);

  GArg a; a.pvec = nullptr; a.rvec = nullptr; a.X = nullptr; a.sX = 0; a.ldx = 0;

  // s0: 1) U = xh @ Wu^T -> g_gin(half) ; 2) h = silu(xh@Wg^T)*U -> g_h(half)
  a.A=pxh; a.sA=0; a.lda=1024; a.B=pwu; a.sB=0; a.ldb=1024;
  a.C=pg;  a.sC=0; a.ldc=4096; a.K=1024;
  gemm_h<E_RAW,__half><<<dim3(32,16,1), 256, GEMM_SMEM, s0>>>(a);
  a.B=pwg; a.C=ph; a.X=pg; a.sX=0; a.ldx=4096;
  gemm_h<E_SWIGLU,__half><<<dim3(32,16,1), 256, GEMM_SMEM, s0>>>(a);
  cudaEventRecord(evA, s0);

  // s1: ktrans -> stage 8 (adjh @ hT)
  cudaStreamWaitEvent(s1, evA, 0);
  ktrans<<<dim3(8,64,16), dim3(32,8), 0, s1>>>(ph, phT);
  cudaEventRecord(evT, s1);
  {
    GArg a8; a8.pvec = alpha; a8.rvec = nullptr; a8.X = nullptr; a8.sX = 0; a8.ldx = 0;
    a8.A=padjh; a8.sA=(long long)2048*2048; a8.lda=2048;
    a8.B=phT;   a8.sB=(long long)256*2048;  a8.ldb=2048;
    a8.C=pcb+256; a8.sC=(long long)2048*1024; a8.ldc=1024; a8.K=2048;
    gemm_h<E_SCALEH,__half><<<dim3(2,16,16), 256, GEMM_SMEM, s1>>>(a8);
  }
  cudaEventRecord(ev8, s1);

  // s2: stage 4 (K proj) -> kcomb
  cudaStreamWaitEvent(s2, evA, 0);
  {
    GArg a4; a4.pvec = nullptr; a4.rvec = nullptr; a4.X = nullptr; a4.sX = 0; a4.ldx = 0;
    a4.A=ph; a4.sA=256; a4.lda=4096; a4.B=pwk; a4.sB=65536; a4.ldb=256;
    a4.C=pk; a4.sC=(long long)2048*256; a4.ldc=256; a4.K=256;
    gemm_h<E_RAW,__half><<<dim3(2,16,16), 256, GEMM_SMEM, s2>>>(a4);
  }
  cudaEventRecord(ev4, s2);
  kcomb<<<32768, 256, 0, s2>>>(ph, pcb, eps);
  cudaEventRecord(evC, s2);

  // s0: 3) Q proj
  a.A=ph; a.sA=256; a.lda=4096; a.B=pwq; a.sB=65536; a.ldb=256;
  a.C=pq; a.sC=(long long)2048*256; a.ldc=256; a.K=256; a.X=nullptr;
  gemm_h<E_RAW,__half><<<dim3(2,16,16), 256, GEMM_SMEM, s0>>>(a);

  // s0: 5) P_unnorm = exp(QK^T/16)*(adj+1e-9) -> g_ph (half)
  cudaStreamWaitEvent(s0, ev4, 0);
  cudaStreamWaitEvent(s0, evH, 0);
  a.A=pq; a.sA=(long long)2048*256; a.lda=256;
  a.B=pk; a.sB=(long long)2048*256; a.ldb=256;
  a.C=pph; a.sC=(long long)2048*2048; a.ldc=2048; a.K=256;
  a.X=padjh; a.sX=(long long)2048*2048; a.ldx=2048;
  gemm_h<E_PEXP,__half><<<dim3(16,16,16), 256, GEMM_SMEM, s0>>>(a);

  // s0: 6) row sums -> reciprocal
  ksum<<<NHD*SEQ, 256, 0, s0>>>(pph, prs);

  // s0: 9) attn_agg = (P_unnorm @ h) * rsum^-1  (needs hT from s1)
  cudaStreamWaitEvent(s0, evT, 0);
  a.A=pph; a.sA=(long long)2048*2048; a.lda=2048;
  a.B=phT; a.sB=(long long)256*2048;  a.ldb=2048;
  a.C=pcb+768; a.sC=(long long)2048*1024; a.ldc=1024; a.K=2048;
  a.X=nullptr; a.rvec=prs;
  gemm_h<E_RSCALE,__half><<<dim3(2,16,16), 256, GEMM_SMEM, s0>>>(a);
  a.rvec=nullptr;

  // join
  cudaStreamWaitEvent(s0, ev8, 0);
  cudaStreamWaitEvent(s0, evC, 0);

  // s0: 10) t = silu(comb @ W1^T)
  a.A=pcb; a.sA=(long long)2048*1024; a.lda=1024;
  a.B=pw1; a.sB=0; a.ldb=1024;
  a.C=pt;  a.sC=(long long)2048*256; a.ldc=256; a.K=1024;
  gemm_h<E_SILU,__half><<<dim3(2,16,16), 256, GEMM_SMEM, s0>>>(a);

  // s0: 11) gin = t @ W2^T (head-interleaved)
  a.A=pt; a.sA=(long long)2048*256; a.lda=256;
  a.B=pw2; a.sB=0; a.ldb=256;
  a.C=pg; a.sC=256; a.ldc=4096; a.K=256;
  gemm_h<E_RAW,__half><<<dim3(2,16,16), 256, GEMM_SMEM, s0>>>(a);

  // s0: 12) out = gin @ Wd^T (fp32 out)
  a.A=pg;  a.sA=0; a.lda=4096;
  a.B=pwd; a.sB=0; a.ldb=4096;
  a.C=out; a.sC=0; a.ldc=1024; a.K=4096;
  gemm_h<E_RAW,float><<<dim3(8,16,1), 256, GEMM_SMEM, s0>>>(a);
}

// round 13
// speedup vs baseline: 1.3408x; 1.0162x over previous
#include <cuda_runtime.h>
#include <cuda_fp16.h>
#include <cstdint>

#define DI __device__ __forceinline__

constexpr int SEQ = 2048, HIDN = 1024, NHD = 16, ITR = 4096, HD = 256;

// ---------------- scratch (device globals; allocation-free) ----------------
__device__ __align__(16) __half g_xh [SEQ * HIDN];
__device__ __align__(16) __half g_wg [ITR * HIDN];
__device__ __align__(16) __half g_wu [ITR * HIDN];
__device__ __align__(16) __half g_wd [HIDN * ITR];
__device__ __align__(16) __half g_wq [NHD * HD * HD];
__device__ __align__(16) __half g_wk [NHD * HD * HD];
__device__ __align__(16) __half g_w1 [HD * 4 * HD];
__device__ __align__(16) __half g_w2 [HD * HD];
__device__ __align__(16) __half g_adjh[(size_t)NHD * SEQ * SEQ];
__device__ __align__(16) __half g_h  [SEQ * ITR];
__device__ __align__(16) __half g_hT [NHD * HD * SEQ];
__device__ __align__(16) __half g_q  [NHD * SEQ * HD];
__device__ __align__(16) __half g_k2 [NHD * SEQ * HD];
__device__ __align__(16) __half g_ph [(size_t)NHD * SEQ * SEQ];   // unnormalized P (half)
__device__ float                g_rs [NHD * SEQ];                  // row sums (atomic)
__device__ __align__(16) __half g_cb [(size_t)NHD * SEQ * 4 * HD];
__device__ __align__(16) __half g_t  [NHD * SEQ * HD];
__device__ __align__(16) __half g_gin[SEQ * ITR];

// ---------------- MUFU-free math ----------------
DI float exp_nm(float x){
  float t = fminf(fmaxf(x * 1.44269504f, -126.f), 126.f);
  float n = rintf(t);
  float y = (t - n) * 0.693147181f;
  float p = 1.f + y*(1.f + y*(0.5f + y*(0.166666667f + y*(0.0416666667f +
            y*(0.00833333333f + y*0.00138888889f)))));
  return p * __int_as_float(((int)n + 127) << 23);
}
DI float recip_nm(float d){
  float r = __int_as_float(0x7EF311C3u - __float_as_uint(d));
  r = r * (2.f - d*r); r = r * (2.f - d*r); r = r * (2.f - d*r);
  return r;
}
DI float silu_nm(float v){ return v * recip_nm(1.f + exp_nm(-v)); }

DI void mma16(float c[4], const uint32_t a[4], const uint32_t b[2]){
  asm volatile("mma.sync.aligned.m16n8k16.row.col.f32.f16.f16.f32 "
    "{%0,%1,%2,%3},{%4,%5,%6,%7},{%8,%9},{%0,%1,%2,%3};\n"
    : "+f"(c[0]),"+f"(c[1]),"+f"(c[2]),"+f"(c[3])
    : "r"(a[0]),"r"(a[1]),"r"(a[2]),"r"(a[3]),"r"(b[0]),"r"(b[1]));
}
DI void ldsm4(uint32_t d[4], uint32_t addr){
  asm volatile("ldmatrix.sync.aligned.m8n8.x4.shared.b16 {%0,%1,%2,%3}, [%4];"
    : "=r"(d[0]),"=r"(d[1]),"=r"(d[2]),"=r"(d[3]) : "r"(addr));
}
DI void ldsm2(uint32_t d[2], uint32_t addr){
  asm volatile("ldmatrix.sync.aligned.m8n8.x2.shared.b16 {%0,%1}, [%2];"
    : "=r"(d[0]),"=r"(d[1]) : "r"(addr));
}
DI uint32_t cvta_s(const void* p){ return (uint32_t)__cvta_generic_to_shared(p); }
DI void cpa16(uint32_t dst, const void* src){
  asm volatile("cp.async.cg.shared.global [%0], [%1], 16;" :: "r"(dst), "l"(src));
}
DI void cpa_commit(){ asm volatile("cp.async.commit_group;" ::: "memory"); }
template<int N> DI void cpa_wait(){ asm volatile("cp.async.wait_group %0;" :: "n"(N) : "memory"); }

// ---------------- batched GEMM: C = A @ B^T, fp16 in gmem, cp.async 4-stage ----------------
// 128x128 CTA tile, 8 warps (2x4), 64x32 warp tile.  (champion config)
enum { E_RAW=0, E_SWIGLU=1, E_PEXP=2, E_SCALEH=3, E_SILU=4, E_RSCALE=5 };

struct GArg {
  const void* A; long long sA; int lda;
  const void* B; long long sB; int ldb;
  void*       C; long long sC; int ldc;
  const void* X; long long sX; int ldx;
  const float* pvec;   // per-batch scale
  const float* rvec;   // per-row sums (b*SEQ + row) for E_RSCALE
  float*       rout;   // per-row atomic sum output for E_PEXP
  int K;
};

template<int EPI, typename CT>
DI void st2(const GArg& g, int b, long long rg, long long cg, float v0, float v1){
  float o0, o1;
  if (EPI == E_RAW){ o0 = v0; o1 = v1; }
  else if (EPI == E_SWIGLU){
    __half2 u = *(const __half2*)((const __half*)g.X + rg*(long long)g.ldx + cg);
    o0 = silu_nm(v0) * __half2float(u.x); o1 = silu_nm(v1) * __half2float(u.y);
  } else if (EPI == E_PEXP){
    __half2 a2 = *(const __half2*)((const __half*)g.X + (long long)b*g.sX + rg*(long long)g.ldx + cg);
    o0 = exp_nm(v0*0.0625f) * (__half2float(a2.x) + 1e-9f);
    o1 = exp_nm(v1*0.0625f) * (__half2float(a2.y) + 1e-9f);
    float s = o0 + o1;
    s += __shfl_xor_sync(0xffffffffu, s, 1);
    s += __shfl_xor_sync(0xffffffffu, s, 2);
    if ((threadIdx.x & 3) == 0) atomicAdd(g.rout + (long long)b*SEQ + rg, s);
  } else if (EPI == E_SCALEH){ float s = g.pvec[b]; o0 = v0*s; o1 = v1*s; }
  else if (EPI == E_RSCALE){
    float s = recip_nm(g.rvec[(long long)b*SEQ + rg]); o0 = v0*s; o1 = v1*s;
  } else { o0 = silu_nm(v0); o1 = silu_nm(v1); }
  CT* p = (CT*)g.C + (long long)b*g.sC + rg*(long long)g.ldc + cg;
  if constexpr (sizeof(CT) == 2) *(__half2*)p = __floats2half2_rn(o0, o1);
  else                           *(float2*)p  = make_float2(o0, o1);
}

constexpr int ROWH = 40;                       // halfs per smem row (80B)
constexpr int TILEH = 128 * ROWH;              // halfs per tile
constexpr int STAGEB = 2 * TILEH * 2;          // bytes per stage (A+B) = 20480
constexpr int NST = 4;
constexpr int GEMM_SMEM = NST * STAGEB;        // 81920

template<int EPI, typename CT>
__global__ void __launch_bounds__(256, 2) gemm_h(GArg g){
  extern __shared__ __half smh[];
  const int b = blockIdx.z;
  const __half* A = (const __half*)g.A + (long long)b*g.sA;
  const __half* B = (const __half*)g.B + (long long)b*g.sB;
  const int m0 = blockIdx.y * 128, n0 = blockIdx.x * 128;
  const int tid = threadIdx.x, lane = tid & 31, wid = tid >> 5;
  const int wm = wid & 1, wn = wid >> 1;
  const int ar = lane >> 2, ac = lane & 3;
  float acc[4][4][4] = {};

  const int rF = tid >> 1;
  const int cB = (tid & 1) * 32;

  const uint32_t smem0 = cvta_s(smh);
  const uint32_t aBase = smem0 + (wm*64 + (lane & 7) + ((lane >> 3) & 1)*8)*(ROWH*2)
                       + ((lane >> 4) & 1)*16;
  const uint32_t bBase = smem0 + TILEH*2 + (wn*32 + (lane & 7))*(ROWH*2)
                       + ((lane >> 3) & 1)*16;
  const int ktiles = g.K >> 5;

  auto issue = [&](int kt){
    if (kt < ktiles){
      int st = kt & (NST - 1);
      uint32_t ds = smem0 + st*STAGEB + rF*(ROWH*2) + cB;
      const char* sa = (const char*)(A + (long long)(m0 + rF)*g.lda + kt*32) + cB;
      const char* sb = (const char*)(B + (long long)(n0 + rF)*g.ldb + kt*32) + cB;
      cpa16(ds,             sa);
      cpa16(ds + 16,        sa + 16);
      cpa16(ds + TILEH*2,      sb);
      cpa16(ds + TILEH*2 + 16, sb + 16);
    }
    cpa_commit();
  };

  issue(0); issue(1); issue(2);

  for (int kt = 0; kt < ktiles; kt++){
    cpa_wait<2>();
    __syncthreads();
    issue(kt + 3);
    const uint32_t so = (uint32_t)(kt & (NST - 1)) * STAGEB;
    #pragma unroll
    for (int kk = 0; kk < 32; kk += 16){
      uint32_t af[4][4], bf[4][2];
      #pragma unroll
      for (int mt = 0; mt < 4; mt++)
        ldsm4(af[mt], aBase + so + mt*16*(ROWH*2) + kk*2);
      #pragma unroll
      for (int nt = 0; nt < 4; nt++)
        ldsm2(bf[nt], bBase + so + nt*8*(ROWH*2) + kk*2);
      #pragma unroll
      for (int mt = 0; mt < 4; mt++)
        #pragma unroll
        for (int nt = 0; nt < 4; nt++)
          mma16(acc[mt][nt], af[mt], bf[nt]);
    }
    __syncthreads();
  }

  #pragma unroll
  for (int mt = 0; mt < 4; mt++)
    #pragma unroll
    for (int nt = 0; nt < 4; nt++){
      long long rg = m0 + wm*64 + mt*16 + ar;
      long long cg = n0 + wn*32 + nt*8 + (ac << 1);
      st2<EPI, CT>(g, b, rg,   cg, acc[mt][nt][0], acc[mt][nt][1]);
      st2<EPI, CT>(g, b, rg+8, cg, acc[mt][nt][2], acc[mt][nt][3]);
    }
}

// ---------------- batched fp32 -> fp16 converters ----------------
struct CvtJob { const float* src; __half* dst; long long n8; };

DI void cvt_body(const CvtJob& j){
  long long i = (long long)blockIdx.x * 256 + threadIdx.x;
  if (i >= j.n8) return;
  float4 a = ((const float4*)j.src)[i*2], c = ((const float4*)j.src)[i*2+1];
  __half2 h0 = __floats2half2_rn(a.x,a.y), h1 = __floats2half2_rn(a.z,a.w);
  __half2 h2 = __floats2half2_rn(c.x,c.y), h3 = __floats2half2_rn(c.z,c.w);
  ((uint4*)j.dst)[i] = make_uint4(*(uint32_t*)&h0, *(uint32_t*)&h1,
                                  *(uint32_t*)&h2, *(uint32_t*)&h3);
}
__global__ void kf2h1(CvtJob j0){ cvt_body(j0); }
__global__ void kf2hN(CvtJob j0, CvtJob j1, CvtJob j2, CvtJob j3){
  CvtJob j = (blockIdx.y==0)?j0:(blockIdx.y==1)?j1:(blockIdx.y==2)?j2:j3;
  cvt_body(j);
}

__global__ void kzero(float* p, int n){
  int i = blockIdx.x * 256 + threadIdx.x;
  if (i < n) p[i] = 0.f;
}

// ---------------- per-head transpose: h (s, h*256+d) half -> hT (h, d, s) half ----------------
__global__ void ktrans(const __half* __restrict__ h, __half* __restrict__ hT){
  __shared__ __half t[32][34];
  int hd = blockIdx.z;
  int s0 = blockIdx.y * 32, d0 = blockIdx.x * 32;
  int tx = threadIdx.x, ty = threadIdx.y;
  #pragma unroll
  for (int i = 0; i < 32; i += 8)
    t[ty+i][tx] = h[(long long)(s0+ty+i)*4096 + hd*256 + d0 + tx];
  __syncthreads();
  #pragma unroll
  for (int i = 0; i < 32; i += 8)
    hT[(long long)hd*(256*2048) + (long long)(d0+ty+i)*2048 + s0 + tx] = t[tx][ty+i];
}

// ---------------- fill comb slices 0 (orig) and 2 (max), half ----------------
__global__ void kcomb(const __half* __restrict__ h, __half* __restrict__ comb,
                      const float* __restrict__ eps){
  long long i = (long long)blockIdx.x * 256 + threadIdx.x;
  int d = (int)(i & 255);
  long long sh = i >> 8;
  int s = (int)(sh & 2047);
  int hd = (int)(sh >> 11);
  float hv = __half2float(h[(long long)s * 4096 + hd * 256 + d]);
  long long base = (long long)hd * (2048 * 1024) + (long long)s * 1024 + d;
  comb[base]       = __float2half_rn((1.f + eps[hd]) * hv);
  comb[base + 512] = __float2half_rn(hv);
}

// ---------------- launch ----------------
extern "C" void kernel_launch(void* const* d_in, const int* in_sizes, int n_in,
                              void* d_out, int out_size){
  const float* x    = (const float*)d_in[0];
  const float* adj  = (const float*)d_in[1];
  const float* Wg   = (const float*)d_in[2];
  const float* Wu   = (const float*)d_in[3];
  const float* Wd   = (const float*)d_in[4];
  const float* eps  = (const float*)d_in[5];
  const float* alpha= (const float*)d_in[6];
  const float* Wq   = (const float*)d_in[7];
  const float* Wk   = (const float*)d_in[8];
  const float* W1   = (const float*)d_in[9];
  const float* W2   = (const float*)d_in[10];
  float* out = (float*)d_out;

  __half *pxh,*pwg,*pwu,*pwd,*pwq,*pwk,*pw1,*pw2,*padjh,*ph,*phT,*pq,*pk,*pph,*pcb,*pt,*pg;
  float *prs;
  cudaGetSymbolAddress((void**)&pxh,  g_xh);
  cudaGetSymbolAddress((void**)&pwg,  g_wg);
  cudaGetSymbolAddress((void**)&pwu,  g_wu);
  cudaGetSymbolAddress((void**)&pwd,  g_wd);
  cudaGetSymbolAddress((void**)&pwq,  g_wq);
  cudaGetSymbolAddress((void**)&pwk,  g_wk);
  cudaGetSymbolAddress((void**)&pw1,  g_w1);
  cudaGetSymbolAddress((void**)&pw2,  g_w2);
  cudaGetSymbolAddress((void**)&padjh,g_adjh);
  cudaGetSymbolAddress((void**)&ph,   g_h);
  cudaGetSymbolAddress((void**)&phT,  g_hT);
  cudaGetSymbolAddress((void**)&pq,   g_q);
  cudaGetSymbolAddress((void**)&pk,   g_k2);
  cudaGetSymbolAddress((void**)&pph,  g_ph);
  cudaGetSymbolAddress((void**)&prs,  g_rs);
  cudaGetSymbolAddress((void**)&pcb,  g_cb);
  cudaGetSymbolAddress((void**)&pt,   g_t);
  cudaGetSymbolAddress((void**)&pg,   g_gin);

  static cudaStream_t s1 = nullptr, s2 = nullptr;
  static cudaEvent_t ev0, evA, evT, ev4, ev8, evC, evH, evW;
  static bool init_done = false;
  if (!init_done){
    cudaFuncSetAttribute(gemm_h<E_RAW,__half>,    cudaFuncAttributeMaxDynamicSharedMemorySize, GEMM_SMEM);
    cudaFuncSetAttribute(gemm_h<E_RAW,float>,     cudaFuncAttributeMaxDynamicSharedMemorySize, GEMM_SMEM);
    cudaFuncSetAttribute(gemm_h<E_SWIGLU,__half>, cudaFuncAttributeMaxDynamicSharedMemorySize, GEMM_SMEM);
    cudaFuncSetAttribute(gemm_h<E_PEXP,__half>,   cudaFuncAttributeMaxDynamicSharedMemorySize, GEMM_SMEM);
    cudaFuncSetAttribute(gemm_h<E_SCALEH,__half>, cudaFuncAttributeMaxDynamicSharedMemorySize, GEMM_SMEM);
    cudaFuncSetAttribute(gemm_h<E_RSCALE,__half>, cudaFuncAttributeMaxDynamicSharedMemorySize, GEMM_SMEM);
    cudaFuncSetAttribute(gemm_h<E_SILU,__half>,   cudaFuncAttributeMaxDynamicSharedMemorySize, GEMM_SMEM);
    cudaStreamCreateWithFlags(&s1, cudaStreamNonBlocking);
    cudaStreamCreateWithFlags(&s2, cudaStreamNonBlocking);
    cudaEventCreateWithFlags(&ev0, cudaEventDisableTiming);
    cudaEventCreateWithFlags(&evA, cudaEventDisableTiming);
    cudaEventCreateWithFlags(&evT, cudaEventDisableTiming);
    cudaEventCreateWithFlags(&ev4, cudaEventDisableTiming);
    cudaEventCreateWithFlags(&ev8, cudaEventDisableTiming);
    cudaEventCreateWithFlags(&evC, cudaEventDisableTiming);
    cudaEventCreateWithFlags(&evH, cudaEventDisableTiming);
    cudaEventCreateWithFlags(&evW, cudaEventDisableTiming);
    init_done = true;
  }
  cudaStream_t s0 = 0;
  auto J = [](const float* s, __half* d, long long n){ CvtJob j{s, d, n >> 3}; return j; };
  CvtJob jz{nullptr, nullptr, 0};

  // s0: zero row sums (must precede PEXP atomics; same stream)
  kzero<<<NHD*SEQ/256, 256, 0, s0>>>(prs, NHD*SEQ);

  // root the fork in the captured stream
  cudaEventRecord(ev0, s0);

  // s1: adjacency -> half
  cudaStreamWaitEvent(s1, ev0, 0);
  kf2h1<<<dim3(32768,1), 256, 0, s1>>>(J(adj, padjh, (long long)NHD*SEQ*SEQ));
  cudaEventRecord(evH, s1);

  // s2: Wk, then Wq/W1/W2/Wd (off critical path)
  cudaStreamWaitEvent(s2, ev0, 0);
  kf2h1<<<dim3(512,1), 256, 0, s2>>>(J(Wk, pwk, (long long)NHD*HD*HD));
  kf2hN<<<dim3(2048,4), 256, 0, s2>>>(J(Wq, pwq, (long long)NHD*HD*HD),
                                      J(W1, pw1, (long long)HD*4*HD),
                                      J(W2, pw2, (long long)HD*HD),
                                      J(Wd, pwd, (long long)HIDN*ITR));
  cudaEventRecord(evW, s2);

  // s0: x, Wu, Wg (needed immediately)
  kf2hN<<<dim3(2048,3), 256, 0, s0>>>(J(x, pxh, (long long)SEQ*HIDN),
                                      J(Wu, pwu, (long long)ITR*HIDN),
                                      J(Wg, pwg, (long long)ITR*HIDN), jz);

  GArg a; a.pvec = nullptr; a.rvec = nullptr; a.rout = nullptr;
  a.X = nullptr; a.sX = 0; a.ldx = 0;

  // s0: 1) U = xh @ Wu^T -> g_gin(half) ; 2) h = silu(xh@Wg^T)*U -> g_h(half)
  a.A=pxh; a.sA=0; a.lda=1024; a.B=pwu; a.sB=0; a.ldb=1024;
  a.C=pg;  a.sC=0; a.ldc=4096; a.K=1024;
  gemm_h<E_RAW,__half><<<dim3(32,16,1), 256, GEMM_SMEM, s0>>>(a);
  a.B=pwg; a.C=ph; a.X=pg; a.sX=0; a.ldx=4096;
  gemm_h<E_SWIGLU,__half><<<dim3(32,16,1), 256, GEMM_SMEM, s0>>>(a);
  cudaEventRecord(evA, s0);

  // s1: ktrans -> stage 8 (adjh @ hT)
  cudaStreamWaitEvent(s1, evA, 0);
  ktrans<<<dim3(8,64,16), dim3(32,8), 0, s1>>>(ph, phT);
  cudaEventRecord(evT, s1);
  {
    GArg a8; a8.pvec = alpha; a8.rvec = nullptr; a8.rout = nullptr;
    a8.X = nullptr; a8.sX = 0; a8.ldx = 0;
    a8.A=padjh; a8.sA=(long long)2048*2048; a8.lda=2048;
    a8.B=phT;   a8.sB=(long long)256*2048;  a8.ldb=2048;
    a8.C=pcb+256; a8.sC=(long long)2048*1024; a8.ldc=1024; a8.K=2048;
    gemm_h<E_SCALEH,__half><<<dim3(2,16,16), 256, GEMM_SMEM, s1>>>(a8);
  }
  cudaEventRecord(ev8, s1);

  // s2: stage 4 (K proj) -> kcomb
  cudaStreamWaitEvent(s2, evA, 0);
  {
    GArg a4; a4.pvec = nullptr; a4.rvec = nullptr; a4.rout = nullptr;
    a4.X = nullptr; a4.sX = 0; a4.ldx = 0;
    a4.A=ph; a4.sA=256; a4.lda=4096; a4.B=pwk; a4.sB=65536; a4.ldb=256;
    a4.C=pk; a4.sC=(long long)2048*256; a4.ldc=256; a4.K=256;
    gemm_h<E_RAW,__half><<<dim3(2,16,16), 256, GEMM_SMEM, s2>>>(a4);
  }
  cudaEventRecord(ev4, s2);
  kcomb<<<32768, 256, 0, s2>>>(ph, pcb, eps);
  cudaEventRecord(evC, s2);

  // s0: 3) Q proj (needs Wq conversion from s2)
  cudaStreamWaitEvent(s0, evW, 0);
  a.A=ph; a.sA=256; a.lda=4096; a.B=pwq; a.sB=65536; a.ldb=256;
  a.C=pq; a.sC=(long long)2048*256; a.ldc=256; a.K=256; a.X=nullptr;
  gemm_h<E_RAW,__half><<<dim3(2,16,16), 256, GEMM_SMEM, s0>>>(a);

  // s0: 5) P_unnorm = exp(QK^T/16)*(adj+1e-9) -> g_ph ; fused row sums -> g_rs
  cudaStreamWaitEvent(s0, ev4, 0);
  cudaStreamWaitEvent(s0, evH, 0);
  a.A=pq; a.sA=(long long)2048*256; a.lda=256;
  a.B=pk; a.sB=(long long)2048*256; a.ldb=256;
  a.C=pph; a.sC=(long long)2048*2048; a.ldc=2048; a.K=256;
  a.X=padjh; a.sX=(long long)2048*2048; a.ldx=2048;
  a.rout=prs;
  gemm_h<E_PEXP,__half><<<dim3(16,16,16), 256, GEMM_SMEM, s0>>>(a);
  a.rout=nullptr;

  // s0: 9) attn_agg = (P_unnorm @ h) * rsum^-1  (needs hT from s1)
  cudaStreamWaitEvent(s0, evT, 0);
  a.A=pph; a.sA=(long long)2048*2048; a.lda=2048;
  a.B=phT; a.sB=(long long)256*2048;  a.ldb=2048;
  a.C=pcb+768; a.sC=(long long)2048*1024; a.ldc=1024; a.K=2048;
  a.X=nullptr; a.rvec=prs;
  gemm_h<E_RSCALE,__half><<<dim3(2,16,16), 256, GEMM_SMEM, s0>>>(a);
  a.rvec=nullptr;

  // join
  cudaStreamWaitEvent(s0, ev8, 0);
  cudaStreamWaitEvent(s0, evC, 0);

  // s0: 10) t = silu(comb @ W1^T)
  a.A=pcb; a.sA=(long long)2048*1024; a.lda=1024;
  a.B=pw1; a.sB=0; a.ldb=1024;
  a.C=pt;  a.sC=(long long)2048*256; a.ldc=256; a.K=1024;
  gemm_h<E_SILU,__half><<<dim3(2,16,16), 256, GEMM_SMEM, s0>>>(a);

  // s0: 11) gin = t @ W2^T (head-interleaved)
  a.A=pt; a.sA=(long long)2048*256; a.lda=256;
  a.B=pw2; a.sB=0; a.ldb=256;
  a.C=pg; a.sC=256; a.ldc=4096; a.K=256;
  gemm_h<E_RAW,__half><<<dim3(2,16,16), 256, GEMM_SMEM, s0>>>(a);

  // s0: 12) out = gin @ Wd^T (fp32 out)
  a.A=pg;  a.sA=0; a.lda=4096;
  a.B=pwd; a.sB=0; a.ldb=4096;
  a.C=out; a.sC=0; a.ldc=1024; a.K=4096;
  gemm_h<E_RAW,float><<<dim3(8,16,1), 256, GEMM_SMEM, s0>>>(a);
}